// round 8
// baseline (speedup 1.0000x reference)
#include <cuda_runtime.h>
#include <cuda_bf16.h>
#include <mma.h>
#include <cstdint>

using namespace nvcuda;

#define BB 8
#define TQ 128
#define TK 128
#define NH 512
#define UNITS 256

// scratch (allocation-free rule: device globals)
__device__ float g_q2[BB * TQ * UNITS];          // [b][t][u]
__device__ float g_k2t[BB * UNITS * TK];         // [b][u][s]  (transposed)

__device__ __forceinline__ float tanha(float x) {
    float y; asm("tanh.approx.f32 %0, %1;" : "=f"(y) : "f"(x)); return y;
}

// ---------------------------------------------------------------------------
// Kernel 1: projections on tensor cores (wmma bf16 hi/lo split, ~fp32 acc).
//   z=0: q = query@W1 -> g_q2 [b][t][u]      (row-major store)
//   z=1: k = value@W2 -> g_k2t [b][u][s]     (col-major store = free transpose)
// Block tile 32x32, BK=32, 128 threads (4 warps: 2m x 2n, warp tile 16x16).
// Grid 512 blocks -> ~3.5 blocks/SM. THREE independent accumulator chains
// (main, corrW, corrX) merged at the end -> MMA chain depth 2/iter.
// Register prefetch queue distance 2; one barrier per iteration.
// C ~= Xhi*Whi + Xhi*Wlo + Xlo*Whi   (lo*lo dropped, ~2^-17 rel err)
// ---------------------------------------------------------------------------
#define GBM 32
#define GBN 32
#define GBK 32
#define XLD 40    // bf16 row stride (80 B: 16B-aligned rows, spread banks)

__global__ __launch_bounds__(128) void proj_kernel(
    const float* __restrict__ Q, const float* __restrict__ V,
    const float* __restrict__ W1, const float* __restrict__ W2)
{
    const int z = blockIdx.z;
    const float* __restrict__ X = z ? V : Q;
    const float* __restrict__ W = z ? W2 : W1;

    __shared__ __nv_bfloat16 Xhi[2][GBM][XLD];
    __shared__ __nv_bfloat16 Xlo[2][GBM][XLD];
    __shared__ __nv_bfloat16 Whi[2][GBK][XLD];
    __shared__ __nv_bfloat16 Wlo[2][GBK][XLD];

    const int tid = threadIdx.x;
    const int m0 = blockIdx.y * GBM;
    const int n0 = blockIdx.x * GBN;

    // staging maps (128 threads): X tile 32x32, W tile 32x32, 8 floats/thread
    const int xr = tid >> 2;              // 0..31
    const int xk = (tid & 3) * 8;         // 0,8,16,24
    const int wr = tid >> 2;              // 0..31
    const int wn = (tid & 3) * 8;         // 0,8,16,24

    const float* __restrict__ Xp = &X[(m0 + xr) * NH + xk];
    const float* __restrict__ Wp = &W[wr * UNITS + n0 + wn];

    // warp layout: 2 (m) x 2 (n); warp tile 16x16
    const int w   = tid >> 5;
    const int wm  = (w & 1) * 16;
    const int wnn = (w >> 1) * 16;

    wmma::fragment<wmma::accumulator, 16, 16, 16, float> macc, ccw, ccx;
    wmma::fill_fragment(macc, 0.0f);
    wmma::fill_fragment(ccw, 0.0f);
    wmma::fill_fragment(ccx, 0.0f);

    // convert this thread's 8 X floats + 8 W floats into hi/lo smem
    auto STAGE = [&](int buf, const float4 xa, const float4 xb,
                               const float4 wa, const float4 wb) {
        const float xf[8] = {xa.x, xa.y, xa.z, xa.w, xb.x, xb.y, xb.z, xb.w};
        const float wf[8] = {wa.x, wa.y, wa.z, wa.w, wb.x, wb.y, wb.z, wb.w};
        #pragma unroll
        for (int j = 0; j < 4; j++) {
            __nv_bfloat162 h = __floats2bfloat162_rn(xf[2*j], xf[2*j+1]);
            __nv_bfloat162 l = __floats2bfloat162_rn(
                xf[2*j]   - __bfloat162float(__low2bfloat16(h)),
                xf[2*j+1] - __bfloat162float(__high2bfloat16(h)));
            *reinterpret_cast<__nv_bfloat162*>(&Xhi[buf][xr][xk + 2*j]) = h;
            *reinterpret_cast<__nv_bfloat162*>(&Xlo[buf][xr][xk + 2*j]) = l;
        }
        #pragma unroll
        for (int j = 0; j < 4; j++) {
            __nv_bfloat162 h = __floats2bfloat162_rn(wf[2*j], wf[2*j+1]);
            __nv_bfloat162 l = __floats2bfloat162_rn(
                wf[2*j]   - __bfloat162float(__low2bfloat16(h)),
                wf[2*j+1] - __bfloat162float(__high2bfloat16(h)));
            *reinterpret_cast<__nv_bfloat162*>(&Whi[buf][wr][wn + 2*j]) = h;
            *reinterpret_cast<__nv_bfloat162*>(&Wlo[buf][wr][wn + 2*j]) = l;
        }
    };

    const int NIT = NH / GBK;             // 16

    // stage tile 0 directly; load tile 1 into the register queue
    {
        float4 xa = *reinterpret_cast<const float4*>(Xp);
        float4 xb = *reinterpret_cast<const float4*>(Xp + 4);
        float4 wa = *reinterpret_cast<const float4*>(Wp);
        float4 wb = *reinterpret_cast<const float4*>(Wp + 4);
        STAGE(0, xa, xb, wa, wb);
    }
    float4 xc0 = *reinterpret_cast<const float4*>(Xp + GBK);
    float4 xc1 = *reinterpret_cast<const float4*>(Xp + GBK + 4);
    float4 wc0 = *reinterpret_cast<const float4*>(Wp + (size_t)GBK * UNITS);
    float4 wc1 = *reinterpret_cast<const float4*>(Wp + (size_t)GBK * UNITS + 4);
    __syncthreads();

    #pragma unroll 2
    for (int it = 0; it < NIT; it++) {
        const int buf = it & 1;

        // issue LDG for tile it+2 (consumed at iter it+1's STAGE)
        float4 xn0, xn1, wn0, wn1;
        const bool more2 = (it + 2) < NIT;
        if (more2) {
            const int ko = (it + 2) * GBK;
            xn0 = *reinterpret_cast<const float4*>(Xp + ko);
            xn1 = *reinterpret_cast<const float4*>(Xp + ko + 4);
            wn0 = *reinterpret_cast<const float4*>(Wp + (size_t)ko * UNITS);
            wn1 = *reinterpret_cast<const float4*>(Wp + (size_t)ko * UNITS + 4);
        }

        // compute on buf: 3 independent accumulation chains
        #pragma unroll
        for (int ks = 0; ks < GBK; ks += 16) {
            wmma::fragment<wmma::matrix_a, 16, 16, 16, __nv_bfloat16, wmma::row_major> ah, al;
            wmma::fragment<wmma::matrix_b, 16, 16, 16, __nv_bfloat16, wmma::row_major> bh, bl;
            wmma::load_matrix_sync(ah, &Xhi[buf][wm][ks], XLD);
            wmma::load_matrix_sync(al, &Xlo[buf][wm][ks], XLD);
            wmma::load_matrix_sync(bh, &Whi[buf][ks][wnn], XLD);
            wmma::load_matrix_sync(bl, &Wlo[buf][ks][wnn], XLD);
            wmma::mma_sync(macc, ah, bh, macc);
            wmma::mma_sync(ccw,  ah, bl, ccw);
            wmma::mma_sync(ccx,  al, bh, ccx);
        }

        // stage tile it+1 from the queue (loaded one iteration earlier)
        if (it + 1 < NIT) STAGE(buf ^ 1, xc0, xc1, wc0, wc1);
        __syncthreads();

        xc0 = xn0; xc1 = xn1; wc0 = wn0; wc1 = wn1;
    }

    // merge correction chains
    #pragma unroll
    for (int i = 0; i < macc.num_elements; i++)
        macc.x[i] += ccw.x[i] + ccx.x[i];

    if (z == 0) {
        // q: row-major [m][u]
        float* p = &g_q2[(size_t)(m0 + wm) * UNITS + n0 + wnn];
        wmma::store_matrix_sync(p, macc, UNITS, wmma::mem_row_major);
    } else {
        // k: col-major store = direct transposed layout [b][u][s]
        const int b  = m0 >> 7;           // 32-row tiles never straddle a batch
        const int s0 = m0 & 127;
        float* p = &g_k2t[((size_t)b * UNITS + n0 + wnn) * TK + s0 + wm];
        wmma::store_matrix_sync(p, macc, TK, wmma::mem_col_major);
    }
}

// ---------------------------------------------------------------------------
// Kernel 2: scores + masked softmax + attn out.
// Grid (TQ/4, B) = (32,8) = 256 blocks, 128 threads (4 warps).
// Thread owns key s_=tid for 4 queries. k read coalesced from g_k2t.
// score = sum_u scale_u * tanh(q_u + k_u).
// ---------------------------------------------------------------------------
#define TT 4
#define NT2 128

__global__ __launch_bounds__(NT2) void score_kernel(
    const void*  __restrict__ maskp,
    const float* __restrict__ scale,
    float* __restrict__ out)
{
    __shared__ float qs[TT][UNITS];
    __shared__ float ss[UNITS];
    __shared__ float sco[TT][TK];

    const int tid = threadIdx.x;
    const int b   = blockIdx.y;
    const int t0  = blockIdx.x * TT;
    const int s_  = tid;

    // stage q rows (4 x 256 floats) and scale
    {
        const float4* q2v = reinterpret_cast<const float4*>(g_q2);
        #pragma unroll
        for (int i = 0; i < 2; i++) {
            int idx = tid + i * NT2;               // 0..255
            int t   = idx >> 6;
            int u4  = idx & 63;
            float4 v = q2v[((size_t)(b * TQ + t0 + t) * UNITS >> 2) + u4];
            *reinterpret_cast<float4*>(&qs[t][u4 * 4]) = v;
        }
        if (tid < 64)
            *reinterpret_cast<float4*>(&ss[tid * 4]) =
                reinterpret_cast<const float4*>(scale)[tid];
    }

    // mask (layout sniffed; lengths >= 64 so word 0 is a valid tag)
    const unsigned int tag = *reinterpret_cast<const unsigned int*>(maskp);
    bool valid;
    if (tag == 1u) {
        valid = reinterpret_cast<const int*>(maskp)[b * TK + s_] != 0;
    } else if (tag == 0x3f800000u) {
        valid = reinterpret_cast<const float*>(maskp)[b * TK + s_] != 0.0f;
    } else {
        valid = reinterpret_cast<const unsigned char*>(maskp)[b * TK + s_] != 0;
    }
    __syncthreads();

    const float* kp = g_k2t + (size_t)b * UNITS * TK + s_;

    float a0 = 0.f, a1 = 0.f, a2 = 0.f, a3 = 0.f;

    float pre[8];
    #pragma unroll
    for (int i = 0; i < 8; i++) pre[i] = __ldg(kp + i * TK);

    for (int u0 = 0; u0 < UNITS; u0 += 8) {
        float cur[8];
        #pragma unroll
        for (int i = 0; i < 8; i++) cur[i] = pre[i];
        if (u0 + 8 < UNITS) {
            #pragma unroll
            for (int i = 0; i < 8; i++) pre[i] = __ldg(kp + (u0 + 8 + i) * TK);
        }
        #pragma unroll
        for (int i = 0; i < 8; i++) {
            float kv = cur[i];
            float sv = ss[u0 + i];
            a0 = fmaf(sv, tanha(qs[0][u0 + i] + kv), a0);
            a1 = fmaf(sv, tanha(qs[1][u0 + i] + kv), a1);
            a2 = fmaf(sv, tanha(qs[2][u0 + i] + kv), a2);
            a3 = fmaf(sv, tanha(qs[3][u0 + i] + kv), a3);
        }
    }

    sco[0][s_] = valid ? a0 : -1e9f;
    sco[1][s_] = valid ? a1 : -1e9f;
    sco[2][s_] = valid ? a2 : -1e9f;
    sco[3][s_] = valid ? a3 : -1e9f;
    __syncthreads();

    // masked softmax: warp w handles query row w
    const int wid  = tid >> 5;
    const int lane = tid & 31;
    {
        float v0 = sco[wid][lane +  0];
        float v1 = sco[wid][lane + 32];
        float v2 = sco[wid][lane + 64];
        float v3 = sco[wid][lane + 96];
        float m = fmaxf(fmaxf(v0, v1), fmaxf(v2, v3));
        #pragma unroll
        for (int o = 16; o; o >>= 1) m = fmaxf(m, __shfl_xor_sync(0xffffffffu, m, o));
        float e0 = __expf(v0 - m), e1 = __expf(v1 - m);
        float e2 = __expf(v2 - m), e3 = __expf(v3 - m);
        float s = e0 + e1 + e2 + e3;
        #pragma unroll
        for (int o = 16; o; o >>= 1) s += __shfl_xor_sync(0xffffffffu, s, o);
        float inv = 1.0f / s;
        e0 *= inv; e1 *= inv; e2 *= inv; e3 *= inv;
        float* aout = out + (size_t)BB * TQ * NH + (size_t)(b * TQ + t0 + wid) * TK;
        aout[lane +  0] = e0;
        aout[lane + 32] = e1;
        aout[lane + 64] = e2;
        aout[lane + 96] = e3;
    }
}

// ---------------------------------------------------------------------------
// Kernel 3: context = attn @ value.
// Grid (NH/128, TQ/16, B) = (4,8,8) = 256 blocks, 128 threads.
// ---------------------------------------------------------------------------
#define CTT 16
#define CTP 20   // padded row stride (16B-aligned rows)

__global__ __launch_bounds__(128) void context_kernel(
    const float* __restrict__ value,
    const float* __restrict__ out_attn,   // attn section of out
    float* __restrict__ out)
{
    __shared__ __align__(16) float a_s[TK][CTP];

    const int tid = threadIdx.x;
    const int h   = blockIdx.x * 128 + tid;
    const int t0  = blockIdx.y * CTT;
    const int b   = blockIdx.z;

    #pragma unroll
    for (int i = 0; i < CTT; i++) {
        int idx = tid + i * 128;
        int t = idx >> 7;
        int s = idx & 127;
        a_s[s][t] = out_attn[(size_t)(b * TQ + t0 + t) * TK + s];
    }
    __syncthreads();

    float acc[CTT] = {};
    const float* vb = value + (size_t)b * TK * NH + h;
    #pragma unroll 4
    for (int s = 0; s < TK; s++) {
        float v = __ldg(vb + (size_t)s * NH);
        #pragma unroll
        for (int t4 = 0; t4 < CTT; t4 += 4) {
            float4 w = *reinterpret_cast<const float4*>(&a_s[s][t4]);
            acc[t4 + 0] = fmaf(w.x, v, acc[t4 + 0]);
            acc[t4 + 1] = fmaf(w.y, v, acc[t4 + 1]);
            acc[t4 + 2] = fmaf(w.z, v, acc[t4 + 2]);
            acc[t4 + 3] = fmaf(w.w, v, acc[t4 + 3]);
        }
    }
    #pragma unroll
    for (int t = 0; t < CTT; t++)
        out[(size_t)(b * TQ + t0 + t) * NH + h] = acc[t];
}

// ---------------------------------------------------------------------------
extern "C" void kernel_launch(void* const* d_in, const int* in_sizes, int n_in,
                              void* d_out, int out_size)
{
    const float* query = (const float*)d_in[0];   // (B,TQ,NH)
    const float* value = (const float*)d_in[1];   // (B,TK,NH)
    const void*  mask  = d_in[2];                 // (B,TK) bool (layout sniffed)
    const float* W1    = (const float*)d_in[3];   // (NH,UNITS)
    const float* W2    = (const float*)d_in[4];   // (NH,UNITS)
    const float* scale = (const float*)d_in[5];   // (UNITS,)
    float* out = (float*)d_out;                   // [context | attn]

    dim3 g1(UNITS / GBN, (BB * TQ) / GBM, 2);     // (8,32,2) = 512 blocks
    proj_kernel<<<g1, 128>>>(query, value, W1, W2);

    dim3 g2(TQ / TT, BB);                         // (32,8)
    score_kernel<<<g2, NT2>>>(mask, scale, out);

    const float* attn_sec = out + (size_t)BB * TQ * NH;
    dim3 g3(NH / 128, TQ / CTT, BB);              // (4,8,8)
    context_kernel<<<g3, 128>>>(value, attn_sec, out);
}

// round 9
// speedup vs baseline: 1.0940x; 1.0940x over previous
#include <cuda_runtime.h>
#include <cuda_bf16.h>
#include <mma.h>
#include <cstdint>

using namespace nvcuda;

#define BB 8
#define TQ 128
#define TK 128
#define NH 512
#define UNITS 256

// scratch (allocation-free rule: device globals)
__device__ float g_q2[BB * TQ * UNITS];          // [b][t][u]
__device__ float g_k2t[BB * UNITS * TK];         // [b][u][s]  (transposed)

__device__ __forceinline__ float tanha(float x) {
    float y; asm("tanh.approx.f32 %0, %1;" : "=f"(y) : "f"(x)); return y;
}

// ---------------------------------------------------------------------------
// Kernel 1: projections on tensor cores (wmma bf16 hi/lo split, ~fp32 acc).
// EXACT R7 configuration (best measured: 23.8 us).
//   z=0: q = query@W1 -> g_q2 [b][t][u]      (row-major store)
//   z=1: k = value@W2 -> g_k2t [b][u][s]     (col-major store = free transpose)
// Block tile 32x64, BK=32, 256 threads (8 warps: 2m x 4n, warp tile 16x16).
// Register prefetch queue distance 2; one barrier per iteration.
// C ~= Xhi*Whi + Xhi*Wlo + Xlo*Whi   (lo*lo dropped, ~2^-17 rel err)
// ---------------------------------------------------------------------------
#define GBM 32
#define GBN 64
#define GBK 32
#define XLD 40    // bf16 row stride (mult of 8)
#define WLD 72

__global__ __launch_bounds__(256) void proj_kernel(
    const float* __restrict__ Q, const float* __restrict__ V,
    const float* __restrict__ W1, const float* __restrict__ W2)
{
    const int z = blockIdx.z;
    const float* __restrict__ X = z ? V : Q;
    const float* __restrict__ W = z ? W2 : W1;

    __shared__ __nv_bfloat16 Xhi[2][GBM][XLD];
    __shared__ __nv_bfloat16 Xlo[2][GBM][XLD];
    __shared__ __nv_bfloat16 Whi[2][GBK][WLD];
    __shared__ __nv_bfloat16 Wlo[2][GBK][WLD];

    const int tid = threadIdx.x;
    const int m0 = blockIdx.y * GBM;
    const int n0 = blockIdx.x * GBN;

    // staging maps: X tile 32x32 (1 float4/thread), W tile 32x64 (2 float4/thread)
    const int xr = tid >> 3;              // 0..31
    const int xk = (tid & 7) * 4;         // 0..28
    const int wr = tid >> 3;              // 0..31
    const int wn = (tid & 7) * 8;         // 0..56

    const float* __restrict__ Xp = &X[(m0 + xr) * NH + xk];
    const float* __restrict__ Wp = &W[wr * UNITS + n0 + wn];

    // warp layout: 2 (m) x 4 (n); warp tile 16x16
    const int w   = tid >> 5;
    const int wm  = (w & 1) * 16;
    const int wnn = (w >> 1) * 16;

    wmma::fragment<wmma::accumulator, 16, 16, 16, float> cfrag;
    wmma::fill_fragment(cfrag, 0.0f);

    // convert and store one tile's worth of this thread's data to smem buf
    auto STAGE = [&](int buf, const float4 xa, const float4 wa, const float4 wb) {
        {
            __nv_bfloat162 h0 = __floats2bfloat162_rn(xa.x, xa.y);
            __nv_bfloat162 l0 = __floats2bfloat162_rn(
                xa.x - __bfloat162float(__low2bfloat16(h0)),
                xa.y - __bfloat162float(__high2bfloat16(h0)));
            __nv_bfloat162 h1 = __floats2bfloat162_rn(xa.z, xa.w);
            __nv_bfloat162 l1 = __floats2bfloat162_rn(
                xa.z - __bfloat162float(__low2bfloat16(h1)),
                xa.w - __bfloat162float(__high2bfloat16(h1)));
            *reinterpret_cast<__nv_bfloat162*>(&Xhi[buf][xr][xk + 0]) = h0;
            *reinterpret_cast<__nv_bfloat162*>(&Xhi[buf][xr][xk + 2]) = h1;
            *reinterpret_cast<__nv_bfloat162*>(&Xlo[buf][xr][xk + 0]) = l0;
            *reinterpret_cast<__nv_bfloat162*>(&Xlo[buf][xr][xk + 2]) = l1;
        }
        const float wf[8] = {wa.x, wa.y, wa.z, wa.w, wb.x, wb.y, wb.z, wb.w};
        #pragma unroll
        for (int j = 0; j < 4; j++) {
            __nv_bfloat162 h = __floats2bfloat162_rn(wf[2*j], wf[2*j+1]);
            __nv_bfloat162 l = __floats2bfloat162_rn(
                wf[2*j]   - __bfloat162float(__low2bfloat16(h)),
                wf[2*j+1] - __bfloat162float(__high2bfloat16(h)));
            *reinterpret_cast<__nv_bfloat162*>(&Whi[buf][wr][wn + 2*j]) = h;
            *reinterpret_cast<__nv_bfloat162*>(&Wlo[buf][wr][wn + 2*j]) = l;
        }
    };

    const int NIT = NH / GBK;             // 16

    // stage tile 0 directly; load tile 1 into the register queue
    {
        float4 xa = *reinterpret_cast<const float4*>(Xp);
        float4 wa = *reinterpret_cast<const float4*>(Wp);
        float4 wb = *reinterpret_cast<const float4*>(Wp + 4);
        STAGE(0, xa, wa, wb);
    }
    float4 xc = *reinterpret_cast<const float4*>(Xp + GBK);
    float4 wc0 = *reinterpret_cast<const float4*>(Wp + (size_t)GBK * UNITS);
    float4 wc1 = *reinterpret_cast<const float4*>(Wp + (size_t)GBK * UNITS + 4);
    __syncthreads();

    #pragma unroll 2
    for (int it = 0; it < NIT; it++) {
        const int buf = it & 1;

        // issue LDG for tile it+2 (consumed at iter it+1's STAGE)
        float4 xn, wn0, wn1;
        const bool more2 = (it + 2) < NIT;
        if (more2) {
            const int ko = (it + 2) * GBK;
            xn  = *reinterpret_cast<const float4*>(Xp + ko);
            wn0 = *reinterpret_cast<const float4*>(Wp + (size_t)ko * UNITS);
            wn1 = *reinterpret_cast<const float4*>(Wp + (size_t)ko * UNITS + 4);
        }

        // compute on buf
        #pragma unroll
        for (int ks = 0; ks < GBK; ks += 16) {
            wmma::fragment<wmma::matrix_a, 16, 16, 16, __nv_bfloat16, wmma::row_major> ah, al;
            wmma::fragment<wmma::matrix_b, 16, 16, 16, __nv_bfloat16, wmma::row_major> bh, bl;
            wmma::load_matrix_sync(ah, &Xhi[buf][wm][ks], XLD);
            wmma::load_matrix_sync(al, &Xlo[buf][wm][ks], XLD);
            wmma::load_matrix_sync(bh, &Whi[buf][ks][wnn], WLD);
            wmma::load_matrix_sync(bl, &Wlo[buf][ks][wnn], WLD);
            wmma::mma_sync(cfrag, ah, bh, cfrag);
            wmma::mma_sync(cfrag, ah, bl, cfrag);
            wmma::mma_sync(cfrag, al, bh, cfrag);
        }

        // stage tile it+1 from the queue (data loaded at iter it-1: already here)
        if (it + 1 < NIT) STAGE(buf ^ 1, xc, wc0, wc1);
        __syncthreads();

        xc = xn; wc0 = wn0; wc1 = wn1;
    }

    if (z == 0) {
        // q: row-major [m][u]
        float* p = &g_q2[(size_t)(m0 + wm) * UNITS + n0 + wnn];
        wmma::store_matrix_sync(p, cfrag, UNITS, wmma::mem_row_major);
    } else {
        // k: col-major store = direct transposed layout [b][u][s]
        const int b  = m0 >> 7;           // 32-row tiles never straddle a batch
        const int s0 = m0 & 127;
        float* p = &g_k2t[((size_t)b * UNITS + n0 + wnn) * TK + s0 + wm];
        wmma::store_matrix_sync(p, cfrag, TK, wmma::mem_col_major);
    }
}

// ---------------------------------------------------------------------------
// Kernel 2: scores + masked softmax + attn out.
// Grid (TQ/4, B) = (32,8) = 256 blocks, 128 threads (4 warps).
// Thread owns key s_=tid for 4 queries. k read coalesced from g_k2t.
// MASK SKIP: invalid keys (s >= len) get -1e9 without computing the 256-u
// tanh loop; warps whose entire 32-key range is masked skip it wholesale
// (~12-25% of score work for lengths uniform in [64,128]).
// ---------------------------------------------------------------------------
#define TT 4
#define NT2 128

__global__ __launch_bounds__(NT2) void score_kernel(
    const void*  __restrict__ maskp,
    const float* __restrict__ scale,
    float* __restrict__ out)
{
    __shared__ float qs[TT][UNITS];
    __shared__ float ss[UNITS];
    __shared__ float sco[TT][TK];

    const int tid = threadIdx.x;
    const int b   = blockIdx.y;
    const int t0  = blockIdx.x * TT;
    const int s_  = tid;

    // stage q rows (4 x 256 floats) and scale
    {
        const float4* q2v = reinterpret_cast<const float4*>(g_q2);
        #pragma unroll
        for (int i = 0; i < 2; i++) {
            int idx = tid + i * NT2;               // 0..255
            int t   = idx >> 6;
            int u4  = idx & 63;
            float4 v = q2v[((size_t)(b * TQ + t0 + t) * UNITS >> 2) + u4];
            *reinterpret_cast<float4*>(&qs[t][u4 * 4]) = v;
        }
        if (tid < 64)
            *reinterpret_cast<float4*>(&ss[tid * 4]) =
                reinterpret_cast<const float4*>(scale)[tid];
    }

    // mask (layout sniffed; lengths >= 64 so word 0 is a valid tag)
    const unsigned int tag = *reinterpret_cast<const unsigned int*>(maskp);
    bool valid;
    if (tag == 1u) {
        valid = reinterpret_cast<const int*>(maskp)[b * TK + s_] != 0;
    } else if (tag == 0x3f800000u) {
        valid = reinterpret_cast<const float*>(maskp)[b * TK + s_] != 0.0f;
    } else {
        valid = reinterpret_cast<const unsigned char*>(maskp)[b * TK + s_] != 0;
    }
    __syncthreads();

    float a0 = 0.f, a1 = 0.f, a2 = 0.f, a3 = 0.f;

    if (valid) {                         // masked keys skip the whole loop
        const float* kp = g_k2t + (size_t)b * UNITS * TK + s_;

        float pre[8];
        #pragma unroll
        for (int i = 0; i < 8; i++) pre[i] = __ldg(kp + i * TK);

        for (int u0 = 0; u0 < UNITS; u0 += 8) {
            float cur[8];
            #pragma unroll
            for (int i = 0; i < 8; i++) cur[i] = pre[i];
            if (u0 + 8 < UNITS) {
                #pragma unroll
                for (int i = 0; i < 8; i++) pre[i] = __ldg(kp + (u0 + 8 + i) * TK);
            }
            #pragma unroll
            for (int i = 0; i < 8; i++) {
                float kv = cur[i];
                float sv = ss[u0 + i];
                a0 = fmaf(sv, tanha(qs[0][u0 + i] + kv), a0);
                a1 = fmaf(sv, tanha(qs[1][u0 + i] + kv), a1);
                a2 = fmaf(sv, tanha(qs[2][u0 + i] + kv), a2);
                a3 = fmaf(sv, tanha(qs[3][u0 + i] + kv), a3);
            }
        }
    }

    sco[0][s_] = valid ? a0 : -1e9f;
    sco[1][s_] = valid ? a1 : -1e9f;
    sco[2][s_] = valid ? a2 : -1e9f;
    sco[3][s_] = valid ? a3 : -1e9f;
    __syncthreads();

    // masked softmax: warp w handles query row w
    const int wid  = tid >> 5;
    const int lane = tid & 31;
    {
        float v0 = sco[wid][lane +  0];
        float v1 = sco[wid][lane + 32];
        float v2 = sco[wid][lane + 64];
        float v3 = sco[wid][lane + 96];
        float m = fmaxf(fmaxf(v0, v1), fmaxf(v2, v3));
        #pragma unroll
        for (int o = 16; o; o >>= 1) m = fmaxf(m, __shfl_xor_sync(0xffffffffu, m, o));
        float e0 = __expf(v0 - m), e1 = __expf(v1 - m);
        float e2 = __expf(v2 - m), e3 = __expf(v3 - m);
        float s = e0 + e1 + e2 + e3;
        #pragma unroll
        for (int o = 16; o; o >>= 1) s += __shfl_xor_sync(0xffffffffu, s, o);
        float inv = 1.0f / s;
        e0 *= inv; e1 *= inv; e2 *= inv; e3 *= inv;
        float* aout = out + (size_t)BB * TQ * NH + (size_t)(b * TQ + t0 + wid) * TK;
        aout[lane +  0] = e0;
        aout[lane + 32] = e1;
        aout[lane + 64] = e2;
        aout[lane + 96] = e3;
    }
}

// ---------------------------------------------------------------------------
// Kernel 3: context = attn @ value.
// Grid (NH/128, TQ/16, B) = (4,8,8) = 256 blocks, 128 threads.
// ---------------------------------------------------------------------------
#define CTT 16
#define CTP 20   // padded row stride (16B-aligned rows)

__global__ __launch_bounds__(128) void context_kernel(
    const float* __restrict__ value,
    const float* __restrict__ out_attn,   // attn section of out
    float* __restrict__ out)
{
    __shared__ __align__(16) float a_s[TK][CTP];

    const int tid = threadIdx.x;
    const int h   = blockIdx.x * 128 + tid;
    const int t0  = blockIdx.y * CTT;
    const int b   = blockIdx.z;

    #pragma unroll
    for (int i = 0; i < CTT; i++) {
        int idx = tid + i * 128;
        int t = idx >> 7;
        int s = idx & 127;
        a_s[s][t] = out_attn[(size_t)(b * TQ + t0 + t) * TK + s];
    }
    __syncthreads();

    float acc[CTT] = {};
    const float* vb = value + (size_t)b * TK * NH + h;
    #pragma unroll 4
    for (int s = 0; s < TK; s++) {
        float v = __ldg(vb + (size_t)s * NH);
        #pragma unroll
        for (int t4 = 0; t4 < CTT; t4 += 4) {
            float4 w = *reinterpret_cast<const float4*>(&a_s[s][t4]);
            acc[t4 + 0] = fmaf(w.x, v, acc[t4 + 0]);
            acc[t4 + 1] = fmaf(w.y, v, acc[t4 + 1]);
            acc[t4 + 2] = fmaf(w.z, v, acc[t4 + 2]);
            acc[t4 + 3] = fmaf(w.w, v, acc[t4 + 3]);
        }
    }
    #pragma unroll
    for (int t = 0; t < CTT; t++)
        out[(size_t)(b * TQ + t0 + t) * NH + h] = acc[t];
}

// ---------------------------------------------------------------------------
extern "C" void kernel_launch(void* const* d_in, const int* in_sizes, int n_in,
                              void* d_out, int out_size)
{
    const float* query = (const float*)d_in[0];   // (B,TQ,NH)
    const float* value = (const float*)d_in[1];   // (B,TK,NH)
    const void*  mask  = d_in[2];                 // (B,TK) bool (layout sniffed)
    const float* W1    = (const float*)d_in[3];   // (NH,UNITS)
    const float* W2    = (const float*)d_in[4];   // (NH,UNITS)
    const float* scale = (const float*)d_in[5];   // (UNITS,)
    float* out = (float*)d_out;                   // [context | attn]

    dim3 g1(UNITS / GBN, (BB * TQ) / GBM, 2);     // (4,32,2) = 256 blocks
    proj_kernel<<<g1, 256>>>(query, value, W1, W2);

    dim3 g2(TQ / TT, BB);                         // (32,8)
    score_kernel<<<g2, NT2>>>(mask, scale, out);

    const float* attn_sec = out + (size_t)BB * TQ * NH;
    dim3 g3(NH / 128, TQ / CTT, BB);              // (4,8,8)
    context_kernel<<<g3, 128>>>(value, attn_sec, out);
}

// round 10
// speedup vs baseline: 1.1569x; 1.0575x over previous
#include <cuda_runtime.h>
#include <cuda_bf16.h>
#include <mma.h>
#include <cstdint>

using namespace nvcuda;

#define BB 8
#define TQ 128
#define TK 128
#define NH 512
#define UNITS 256

#define NCHUNK 4
#define BPC (BB / NCHUNK)    // batches per chunk = 2

// scratch (allocation-free rule: device globals)
__device__ float g_q2[BB * TQ * UNITS];          // [b][t][u]
__device__ float g_k2t[BB * UNITS * TK];         // [b][u][s]  (transposed)

__device__ __forceinline__ float tanha(float x) {
    float y; asm("tanh.approx.f32 %0, %1;" : "=f"(y) : "f"(x)); return y;
}

// ---------------------------------------------------------------------------
// Kernel 1: projections on tensor cores (wmma bf16 hi/lo split, ~fp32 acc).
// R7 configuration (best measured), now per-chunk: handles batches
// [b0, b0+BPC). Block tile 32x64, BK=32, 256 threads (8 warps 2m x 4n).
// Register prefetch queue distance 2; one barrier per iteration.
// C ~= Xhi*Whi + Xhi*Wlo + Xlo*Whi   (lo*lo dropped, ~2^-17 rel err)
// ---------------------------------------------------------------------------
#define GBM 32
#define GBN 64
#define GBK 32
#define XLD 40    // bf16 row stride (mult of 8)
#define WLD 72

__global__ __launch_bounds__(256) void proj_kernel(
    const float* __restrict__ Q, const float* __restrict__ V,
    const float* __restrict__ W1, const float* __restrict__ W2, int b0)
{
    const int z = blockIdx.z;
    const float* __restrict__ X = z ? V : Q;
    const float* __restrict__ W = z ? W2 : W1;

    __shared__ __nv_bfloat16 Xhi[2][GBM][XLD];
    __shared__ __nv_bfloat16 Xlo[2][GBM][XLD];
    __shared__ __nv_bfloat16 Whi[2][GBK][WLD];
    __shared__ __nv_bfloat16 Wlo[2][GBK][WLD];

    const int tid = threadIdx.x;
    const int m0 = b0 * TQ + blockIdx.y * GBM;
    const int n0 = blockIdx.x * GBN;

    // staging maps: X tile 32x32 (1 float4/thread), W tile 32x64 (2 float4/thread)
    const int xr = tid >> 3;              // 0..31
    const int xk = (tid & 7) * 4;         // 0..28
    const int wr = tid >> 3;              // 0..31
    const int wn = (tid & 7) * 8;         // 0..56

    const float* __restrict__ Xp = &X[(m0 + xr) * NH + xk];
    const float* __restrict__ Wp = &W[wr * UNITS + n0 + wn];

    // warp layout: 2 (m) x 4 (n); warp tile 16x16
    const int w   = tid >> 5;
    const int wm  = (w & 1) * 16;
    const int wnn = (w >> 1) * 16;

    wmma::fragment<wmma::accumulator, 16, 16, 16, float> cfrag;
    wmma::fill_fragment(cfrag, 0.0f);

    auto STAGE = [&](int buf, const float4 xa, const float4 wa, const float4 wb) {
        {
            __nv_bfloat162 h0 = __floats2bfloat162_rn(xa.x, xa.y);
            __nv_bfloat162 l0 = __floats2bfloat162_rn(
                xa.x - __bfloat162float(__low2bfloat16(h0)),
                xa.y - __bfloat162float(__high2bfloat16(h0)));
            __nv_bfloat162 h1 = __floats2bfloat162_rn(xa.z, xa.w);
            __nv_bfloat162 l1 = __floats2bfloat162_rn(
                xa.z - __bfloat162float(__low2bfloat16(h1)),
                xa.w - __bfloat162float(__high2bfloat16(h1)));
            *reinterpret_cast<__nv_bfloat162*>(&Xhi[buf][xr][xk + 0]) = h0;
            *reinterpret_cast<__nv_bfloat162*>(&Xhi[buf][xr][xk + 2]) = h1;
            *reinterpret_cast<__nv_bfloat162*>(&Xlo[buf][xr][xk + 0]) = l0;
            *reinterpret_cast<__nv_bfloat162*>(&Xlo[buf][xr][xk + 2]) = l1;
        }
        const float wf[8] = {wa.x, wa.y, wa.z, wa.w, wb.x, wb.y, wb.z, wb.w};
        #pragma unroll
        for (int j = 0; j < 4; j++) {
            __nv_bfloat162 h = __floats2bfloat162_rn(wf[2*j], wf[2*j+1]);
            __nv_bfloat162 l = __floats2bfloat162_rn(
                wf[2*j]   - __bfloat162float(__low2bfloat16(h)),
                wf[2*j+1] - __bfloat162float(__high2bfloat16(h)));
            *reinterpret_cast<__nv_bfloat162*>(&Whi[buf][wr][wn + 2*j]) = h;
            *reinterpret_cast<__nv_bfloat162*>(&Wlo[buf][wr][wn + 2*j]) = l;
        }
    };

    const int NIT = NH / GBK;             // 16

    {
        float4 xa = *reinterpret_cast<const float4*>(Xp);
        float4 wa = *reinterpret_cast<const float4*>(Wp);
        float4 wb = *reinterpret_cast<const float4*>(Wp + 4);
        STAGE(0, xa, wa, wb);
    }
    float4 xc = *reinterpret_cast<const float4*>(Xp + GBK);
    float4 wc0 = *reinterpret_cast<const float4*>(Wp + (size_t)GBK * UNITS);
    float4 wc1 = *reinterpret_cast<const float4*>(Wp + (size_t)GBK * UNITS + 4);
    __syncthreads();

    #pragma unroll 2
    for (int it = 0; it < NIT; it++) {
        const int buf = it & 1;

        float4 xn, wn0, wn1;
        const bool more2 = (it + 2) < NIT;
        if (more2) {
            const int ko = (it + 2) * GBK;
            xn  = *reinterpret_cast<const float4*>(Xp + ko);
            wn0 = *reinterpret_cast<const float4*>(Wp + (size_t)ko * UNITS);
            wn1 = *reinterpret_cast<const float4*>(Wp + (size_t)ko * UNITS + 4);
        }

        #pragma unroll
        for (int ks = 0; ks < GBK; ks += 16) {
            wmma::fragment<wmma::matrix_a, 16, 16, 16, __nv_bfloat16, wmma::row_major> ah, al;
            wmma::fragment<wmma::matrix_b, 16, 16, 16, __nv_bfloat16, wmma::row_major> bh, bl;
            wmma::load_matrix_sync(ah, &Xhi[buf][wm][ks], XLD);
            wmma::load_matrix_sync(al, &Xlo[buf][wm][ks], XLD);
            wmma::load_matrix_sync(bh, &Whi[buf][ks][wnn], WLD);
            wmma::load_matrix_sync(bl, &Wlo[buf][ks][wnn], WLD);
            wmma::mma_sync(cfrag, ah, bh, cfrag);
            wmma::mma_sync(cfrag, ah, bl, cfrag);
            wmma::mma_sync(cfrag, al, bh, cfrag);
        }

        if (it + 1 < NIT) STAGE(buf ^ 1, xc, wc0, wc1);
        __syncthreads();

        xc = xn; wc0 = wn0; wc1 = wn1;
    }

    if (z == 0) {
        float* p = &g_q2[(size_t)(m0 + wm) * UNITS + n0 + wnn];
        wmma::store_matrix_sync(p, cfrag, UNITS, wmma::mem_row_major);
    } else {
        const int b  = m0 >> 7;           // 32-row tiles never straddle a batch
        const int s0 = m0 & 127;
        float* p = &g_k2t[((size_t)b * UNITS + n0 + wnn) * TK + s0 + wm];
        wmma::store_matrix_sync(p, cfrag, TK, wmma::mem_col_major);
    }
}

// ---------------------------------------------------------------------------
// Kernel 2: scores + masked softmax + attn out (per-chunk).
// Grid (TQ/4, BPC), 128 threads (4 warps). Thread owns key s_=tid for 4
// queries; k read coalesced from g_k2t. Masked keys skip the tanh loop.
// ---------------------------------------------------------------------------
#define TT 4
#define NT2 128

__global__ __launch_bounds__(NT2) void score_kernel(
    const void*  __restrict__ maskp,
    const float* __restrict__ scale,
    float* __restrict__ out, int b0)
{
    __shared__ float qs[TT][UNITS];
    __shared__ float ss[UNITS];
    __shared__ float sco[TT][TK];

    const int tid = threadIdx.x;
    const int b   = b0 + blockIdx.y;
    const int t0  = blockIdx.x * TT;
    const int s_  = tid;

    {
        const float4* q2v = reinterpret_cast<const float4*>(g_q2);
        #pragma unroll
        for (int i = 0; i < 2; i++) {
            int idx = tid + i * NT2;               // 0..255
            int t   = idx >> 6;
            int u4  = idx & 63;
            float4 v = q2v[((size_t)(b * TQ + t0 + t) * UNITS >> 2) + u4];
            *reinterpret_cast<float4*>(&qs[t][u4 * 4]) = v;
        }
        if (tid < 64)
            *reinterpret_cast<float4*>(&ss[tid * 4]) =
                reinterpret_cast<const float4*>(scale)[tid];
    }

    // mask (layout sniffed; lengths >= 64 so word 0 is a valid tag)
    const unsigned int tag = *reinterpret_cast<const unsigned int*>(maskp);
    bool valid;
    if (tag == 1u) {
        valid = reinterpret_cast<const int*>(maskp)[b * TK + s_] != 0;
    } else if (tag == 0x3f800000u) {
        valid = reinterpret_cast<const float*>(maskp)[b * TK + s_] != 0.0f;
    } else {
        valid = reinterpret_cast<const unsigned char*>(maskp)[b * TK + s_] != 0;
    }
    __syncthreads();

    float a0 = 0.f, a1 = 0.f, a2 = 0.f, a3 = 0.f;

    if (valid) {
        const float* kp = g_k2t + (size_t)b * UNITS * TK + s_;

        float pre[8];
        #pragma unroll
        for (int i = 0; i < 8; i++) pre[i] = __ldg(kp + i * TK);

        for (int u0 = 0; u0 < UNITS; u0 += 8) {
            float cur[8];
            #pragma unroll
            for (int i = 0; i < 8; i++) cur[i] = pre[i];
            if (u0 + 8 < UNITS) {
                #pragma unroll
                for (int i = 0; i < 8; i++) pre[i] = __ldg(kp + (u0 + 8 + i) * TK);
            }
            #pragma unroll
            for (int i = 0; i < 8; i++) {
                float kv = cur[i];
                float sv = ss[u0 + i];
                a0 = fmaf(sv, tanha(qs[0][u0 + i] + kv), a0);
                a1 = fmaf(sv, tanha(qs[1][u0 + i] + kv), a1);
                a2 = fmaf(sv, tanha(qs[2][u0 + i] + kv), a2);
                a3 = fmaf(sv, tanha(qs[3][u0 + i] + kv), a3);
            }
        }
    }

    sco[0][s_] = valid ? a0 : -1e9f;
    sco[1][s_] = valid ? a1 : -1e9f;
    sco[2][s_] = valid ? a2 : -1e9f;
    sco[3][s_] = valid ? a3 : -1e9f;
    __syncthreads();

    // masked softmax: warp w handles query row w
    const int wid  = tid >> 5;
    const int lane = tid & 31;
    {
        float v0 = sco[wid][lane +  0];
        float v1 = sco[wid][lane + 32];
        float v2 = sco[wid][lane + 64];
        float v3 = sco[wid][lane + 96];
        float m = fmaxf(fmaxf(v0, v1), fmaxf(v2, v3));
        #pragma unroll
        for (int o = 16; o; o >>= 1) m = fmaxf(m, __shfl_xor_sync(0xffffffffu, m, o));
        float e0 = __expf(v0 - m), e1 = __expf(v1 - m);
        float e2 = __expf(v2 - m), e3 = __expf(v3 - m);
        float s = e0 + e1 + e2 + e3;
        #pragma unroll
        for (int o = 16; o; o >>= 1) s += __shfl_xor_sync(0xffffffffu, s, o);
        float inv = 1.0f / s;
        e0 *= inv; e1 *= inv; e2 *= inv; e3 *= inv;
        float* aout = out + (size_t)BB * TQ * NH + (size_t)(b * TQ + t0 + wid) * TK;
        aout[lane +  0] = e0;
        aout[lane + 32] = e1;
        aout[lane + 64] = e2;
        aout[lane + 96] = e3;
    }
}

// ---------------------------------------------------------------------------
// Kernel 3: context = attn @ value (per-chunk).
// Grid (NH/128, TQ/16, BPC), 128 threads.
// ---------------------------------------------------------------------------
#define CTT 16
#define CTP 20   // padded row stride (16B-aligned rows)

__global__ __launch_bounds__(128) void context_kernel(
    const float* __restrict__ value,
    const float* __restrict__ out_attn,   // attn section of out
    float* __restrict__ out, int b0)
{
    __shared__ __align__(16) float a_s[TK][CTP];

    const int tid = threadIdx.x;
    const int h   = blockIdx.x * 128 + tid;
    const int t0  = blockIdx.y * CTT;
    const int b   = b0 + blockIdx.z;

    #pragma unroll
    for (int i = 0; i < CTT; i++) {
        int idx = tid + i * 128;
        int t = idx >> 7;
        int s = idx & 127;
        a_s[s][t] = out_attn[(size_t)(b * TQ + t0 + t) * TK + s];
    }
    __syncthreads();

    float acc[CTT] = {};
    const float* vb = value + (size_t)b * TK * NH + h;
    #pragma unroll 4
    for (int s = 0; s < TK; s++) {
        float v = __ldg(vb + (size_t)s * NH);
        #pragma unroll
        for (int t4 = 0; t4 < CTT; t4 += 4) {
            float4 w = *reinterpret_cast<const float4*>(&a_s[s][t4]);
            acc[t4 + 0] = fmaf(w.x, v, acc[t4 + 0]);
            acc[t4 + 1] = fmaf(w.y, v, acc[t4 + 1]);
            acc[t4 + 2] = fmaf(w.z, v, acc[t4 + 2]);
            acc[t4 + 3] = fmaf(w.w, v, acc[t4 + 3]);
        }
    }
    #pragma unroll
    for (int t = 0; t < CTT; t++)
        out[(size_t)(b * TQ + t0 + t) * NH + h] = acc[t];
}

// ---------------------------------------------------------------------------
// Launch: 4 independent per-chunk chains (proj -> score -> context), fanned
// out over 4 streams via the standard capture-legal fork/join event pattern.
// Streams/events are host objects created once (no device allocation).
// ---------------------------------------------------------------------------
extern "C" void kernel_launch(void* const* d_in, const int* in_sizes, int n_in,
                              void* d_out, int out_size)
{
    const float* query = (const float*)d_in[0];   // (B,TQ,NH)
    const float* value = (const float*)d_in[1];   // (B,TK,NH)
    const void*  mask  = d_in[2];                 // (B,TK) bool (layout sniffed)
    const float* W1    = (const float*)d_in[3];   // (NH,UNITS)
    const float* W2    = (const float*)d_in[4];   // (NH,UNITS)
    const float* scale = (const float*)d_in[5];   // (UNITS,)
    float* out = (float*)d_out;                   // [context | attn]
    const float* attn_sec = out + (size_t)BB * TQ * NH;

    static cudaStream_t side[NCHUNK - 1] = {};
    static cudaEvent_t  evf[NCHUNK - 1] = {};
    static cudaEvent_t  evj[NCHUNK - 1] = {};
    if (side[0] == nullptr) {
        for (int i = 0; i < NCHUNK - 1; i++) {
            cudaStreamCreateWithFlags(&side[i], cudaStreamNonBlocking);
            cudaEventCreateWithFlags(&evf[i], cudaEventDisableTiming);
            cudaEventCreateWithFlags(&evj[i], cudaEventDisableTiming);
        }
    }

    // fork side streams off the capture (default) stream
    for (int i = 0; i < NCHUNK - 1; i++) {
        cudaEventRecord(evf[i], 0);
        cudaStreamWaitEvent(side[i], evf[i], 0);
    }

    for (int c = 0; c < NCHUNK; c++) {
        cudaStream_t st = (c == 0) ? 0 : side[c - 1];
        const int b0 = c * BPC;

        dim3 g1(UNITS / GBN, (BPC * TQ) / GBM, 2);    // (4,8,2) = 64 blocks
        proj_kernel<<<g1, 256, 0, st>>>(query, value, W1, W2, b0);

        dim3 g2(TQ / TT, BPC);                        // (32,2) = 64 blocks
        score_kernel<<<g2, NT2, 0, st>>>(mask, scale, out, b0);

        dim3 g3(NH / 128, TQ / CTT, BPC);             // (4,8,2) = 64 blocks
        context_kernel<<<g3, 128, 0, st>>>(value, attn_sec, out, b0);
    }

    // join side streams back into the capture stream
    for (int i = 0; i < NCHUNK - 1; i++) {
        cudaEventRecord(evj[i], side[i]);
        cudaStreamWaitEvent(0, evj[i], 0);
    }
}